// round 8
// baseline (speedup 1.0000x reference)
#include <cuda_runtime.h>
#include <stdint.h>

// Problem constants
#define BATCH        8
#define DOF          300000
#define NFIX         3000
#define NEWTON_ITERS 6
#define D4           (DOF / 4)            // 75000 float4 per batch row
#define BX           148                  // blocks per batch row
#define TPB          256
#define STRIDE       (BX * TPB)           // 37888 float4-threads per batch row
#define CHUNKS       2                    // 2*37888 = 75776 >= 75000
#define NMON         6                    // GG, PP, QQ, GP, GQ, PQ
#define NV           (4 * CHUNKS)         // 8 values per thread

// Grid = BX*BATCH = 1184 blocks; with 8 resident blocks/SM on 152 SMs there
// are 1216 slots, so the persistent spin-barrier cannot deadlock.

// alphas[t] = max(0.5^t, 0.05)
__constant__ float c_alpha[8] = {1.0f, 0.5f, 0.25f, 0.125f, 0.0625f, 0.05f, 0.05f, 0.05f};

// Device globals (allocation-free scratch).
//
// g_sum: 3-buffer rotation; iteration it accumulates into buf it%3 via
// relaxed float red.add. Reads of buf (it%3) happen between barrier it and
// that block's arrival at barrier it+1, so after passing barrier it the bx0
// block may safely zero buf ((it+2)%3) (== buf ((it-1)%3), whose reads all
// completed before barrier it); the zero is release-ordered by bx0's arrival
// at barrier it+1, before any block starts iteration it+2's accumulation.
// Replay safety: it=4 zeroes buf0, it=5 zeroes buf1, next launch's it=0
// zeroes buf2 (before its first use at iteration 2). First launch: static 0.
//
// g_cnt: deferred-reset counters (replay-safe): after passing barrier it,
// bx0 resets counter it-1 (provably no block still polls it); at it=0 it
// resets counter 5 (stale from previous replay; arrivals at counter 5
// require passing barriers 1..4 first, each ordered after the reset).
__device__ float g_sum[3][NMON * BATCH];
__device__ int   g_cnt[NEWTON_ITERS][BATCH];

__device__ __forceinline__ float frcp_approx(float x)
{
    float r;
    asm("rcp.approx.f32 %0, %1;" : "=f"(r) : "f"(x));
    return r;
}
__device__ __forceinline__ void redAddRelaxedF32(float* a, float v)
{
    asm volatile("red.relaxed.gpu.global.add.f32 [%0], %1;" :: "l"(a), "f"(v) : "memory");
}
__device__ __forceinline__ void redAddReleaseS32(int* a, int v)
{
    asm volatile("red.release.gpu.global.add.s32 [%0], %1;" :: "l"(a), "r"(v) : "memory");
}
__device__ __forceinline__ int ldAcquireS32(const int* a)
{
    int v;
    asm volatile("ld.acquire.gpu.global.s32 %0, [%1];" : "=r"(v) : "l"(a) : "memory");
    return v;
}

// ---------------------------------------------------------------------------
// Persistent Newton solver, single launch. u and du live in registers.
//   g = free*(f - (k*u + 0.4u^3)); h = k + 1.2u^2; du = -g/h
//   monomials G=g, P=u*du^2, Q=du^3 -> 6 sums; trial residual is the exact
//   polynomial r(a) = (1+a)G - 1.2a^2 P - 0.4a^3 Q, so all 8 trial norms^2
//   are quadratic forms in the 6 sums (GG also = init norm^2).
//   Per-batch barrier: relaxed red.add of the 6 block sums, release-inc of
//   the arrival counter, acquire-poll with nanosleep backoff. No membar.gl
//   anywhere -> no CCTL.IVALL -> f/kd stay L1-resident across iterations.
//   8 resident blocks/SM (32-reg cap) -> 64 warps/SM to hide latency.
__global__ void __launch_bounds__(TPB, 8)
kSolve(const float* __restrict__ f,
       const float* __restrict__ u0,
       const float* __restrict__ kd,
       const int*   __restrict__ fixed_dofs,
       float* __restrict__ out)
{
    const int tid = threadIdx.x;
    const int bx  = blockIdx.x;
    const int b   = blockIdx.y;
    const int i0  = bx * TPB + tid;

    const float4* f4 = reinterpret_cast<const float4*>(f) + (size_t)b * D4;
    const float4* k4 = reinterpret_cast<const float4*>(kd);
    const float4* u4 = reinterpret_cast<const float4*>(u0) + (size_t)b * D4;

    __shared__ uint32_t maskw[CHUNKS * 32];   // 2 ranges x 1024 dofs
    __shared__ float    sred[8][NMON];
    __shared__ float    s_alpha;

    // ---- build this block's fixed-dof bitmap (once) ----
    if (tid < CHUNKS * 32) maskw[tid] = 0u;
    __syncthreads();
    for (int j = tid; j < NFIX; j += TPB) {
        int d = fixed_dofs[j];
#pragma unroll
        for (int c = 0; c < CHUNKS; c++) {
            int lo = (bx * TPB + c * STRIDE) * 4;
            unsigned off = (unsigned)(d - lo);
            if (off < 1024u)
                atomicOr(&maskw[c * 32 + (off >> 5)], 1u << (off & 31));
        }
    }
    __syncthreads();

    uint32_t nibs = 0;   // 4 fixed-bits per chunk
    float u[NV];
    float du[NV];
#pragma unroll
    for (int c = 0; c < CHUNKS; c++) {
        int i  = i0 + c * STRIDE;
        int ic = (i < D4) ? i : (D4 - 1);
        float4 uu = u4[ic];
        u[c * 4 + 0] = uu.x; u[c * 4 + 1] = uu.y;
        u[c * 4 + 2] = uu.z; u[c * 4 + 3] = uu.w;
        uint32_t w  = maskw[c * 32 + (tid >> 3)];
        uint32_t nb = (w >> ((tid & 7) * 4)) & 0xFu;
        if (i >= D4) nb = 0xFu;            // tail threads contribute nothing
        nibs |= nb << (c * 4);
    }

    for (int it = 0; it < NEWTON_ITERS; it++) {
        float acc[NMON];
#pragma unroll
        for (int m = 0; m < NMON; m++) acc[m] = 0.0f;

        // ---- compute monomial partial sums; du stays in registers ----
#pragma unroll
        for (int c = 0; c < CHUNKS; c++) {
            int i  = i0 + c * STRIDE;
            int ic = (i < D4) ? i : (D4 - 1);
            float4 ff = f4[ic];
            float4 kk = k4[ic];
            float fa[4] = {ff.x, ff.y, ff.z, ff.w};
            float ka[4] = {kk.x, kk.y, kk.z, kk.w};
#pragma unroll
            for (int j = 0; j < 4; j++) {
                float fr = ((nibs >> (c * 4 + j)) & 1u) ? 0.0f : 1.0f;
                float uu = u[c * 4 + j];
                float u2 = uu * uu;
                float t  = fmaf(0.4f, u2, ka[j]);
                float g  = fr * fmaf(-uu, t, fa[j]);
                float h  = fmaf(1.2f, u2, ka[j]);
                float v  = -g * frcp_approx(h);
                du[c * 4 + j] = v;
                float v2 = v * v;
                float P  = uu * v2;
                float Q  = v * v2;
                acc[0] = fmaf(g, g, acc[0]);
                acc[1] = fmaf(P, P, acc[1]);
                acc[2] = fmaf(Q, Q, acc[2]);
                acc[3] = fmaf(g, P, acc[3]);
                acc[4] = fmaf(g, Q, acc[4]);
                acc[5] = fmaf(P, Q, acc[5]);
            }
        }

        // ---- deterministic block reduction of 6 accumulators ----
#pragma unroll
        for (int m = 0; m < NMON; m++) {
#pragma unroll
            for (int o = 16; o; o >>= 1)
                acc[m] += __shfl_down_sync(0xffffffffu, acc[m], o);
        }
        if ((tid & 31) == 0) {
            int w = tid >> 5;
#pragma unroll
            for (int m = 0; m < NMON; m++) sred[w][m] = acc[m];
        }
        __syncthreads();
        const int buf = it % 3;
        if (tid < NMON) {
            float s = 0.0f;
#pragma unroll
            for (int w = 0; w < 8; w++) s += sred[w][tid];
            redAddRelaxedF32(&g_sum[buf][tid * BATCH + b], s);
        }
        __syncthreads();

        // ---- per-batch barrier: release arrive, acquire poll + backoff ----
        if (tid == 0) {
            redAddReleaseS32(&g_cnt[it][b], 1);
            while (ldAcquireS32(&g_cnt[it][b]) < BX) __nanosleep(64);
        }
        __syncthreads();

        // bx0 housekeeping: reset old counter, zero the it+2 sum buffer.
        // Both are release-ordered by bx0's arrival at barrier it+1.
        if (bx == 0 && tid == 0) {
            int prev = (it == 0) ? (NEWTON_ITERS - 1) : (it - 1);
            __stcg(&g_cnt[prev][b], 0);
            float* z = &g_sum[(it + 2) % 3][0];
#pragma unroll
            for (int m = 0; m < NMON; m++) __stcg(&z[m * BATCH + b], 0.0f);
        }

        // ---- alpha from the 6 global sums (quadratic form per trial) ----
        if (tid == 0) {
            const float* S = &g_sum[buf][0];
            float gg = __ldcg(&S[0 * BATCH + b]);
            float pp = __ldcg(&S[1 * BATCH + b]);
            float qq = __ldcg(&S[2 * BATCH + b]);
            float gp = __ldcg(&S[3 * BATCH + b]);
            float gq = __ldcg(&S[4 * BATCH + b]);
            float pq = __ldcg(&S[5 * BATCH + b]);
            float a = 0.05f;                 // ALPHA_MIN
#pragma unroll
            for (int tr = 7; tr >= 0; tr--) {
                float at = c_alpha[tr];
                float c1 = 1.0f + at;
                float c2 = -1.2f * at * at;
                float c3 = -0.4f * at * at * at;
                float n2 = c1 * c1 * gg + c2 * c2 * pp + c3 * c3 * qq
                         + 2.0f * (c1 * c2 * gp + c1 * c3 * gq + c2 * c3 * pq);
                if (n2 < gg) a = at;         // downward scan -> first improving
            }
            s_alpha = a;
        }
        __syncthreads();

        // ---- update: u += alpha * du ----
        float aB = s_alpha;
#pragma unroll
        for (int x = 0; x < NV; x++)
            u[x] = fmaf(aB, du[x], u[x]);
    }

    // ---- final store ----
    float4* o4 = reinterpret_cast<float4*>(out) + (size_t)b * D4;
#pragma unroll
    for (int c = 0; c < CHUNKS; c++) {
        int i = i0 + c * STRIDE;
        if (i < D4) {
            float4 o = {u[c * 4 + 0], u[c * 4 + 1], u[c * 4 + 2], u[c * 4 + 3]};
            o4[i] = o;
        }
    }
}

// ---------------------------------------------------------------------------
extern "C" void kernel_launch(void* const* d_in, const int* in_sizes, int n_in,
                              void* d_out, int out_size)
{
    const float* f  = (const float*)d_in[0];   // external_forces [B, DOF]
    const float* u0 = (const float*)d_in[1];   // u0              [B, DOF]
    const float* kd = (const float*)d_in[2];   // k_diag          [DOF]
    const int*   fd = (const int*)d_in[3];     // fixed_dofs      [NFIX]

    kSolve<<<dim3(BX, BATCH), TPB>>>(f, u0, kd, fd, (float*)d_out);
}

// round 9
// speedup vs baseline: 1.1231x; 1.1231x over previous
#include <cuda_runtime.h>
#include <stdint.h>

// Problem constants
#define BATCH        8
#define DOF          300000
#define NFIX         3000
#define NEWTON_ITERS 6
#define D4           (DOF / 4)            // 75000 float4 per batch row
#define BX           74                   // blocks per batch row
#define TPB          256
#define STRIDE       (BX * TPB)           // 18944 float4-threads per batch row
#define CHUNKS       4                    // 4*18944 = 75776 >= 75000
#define NMON         6                    // GG, PP, QQ, GP, GQ, PQ
#define NV           (4 * CHUNKS)         // 16 values per thread

// Grid = 592 blocks; 4 resident blocks/SM on 152 SMs = 608 slots >= 592,
// so the persistent spin-barrier cannot deadlock.

// alphas[t] = max(0.5^t, 0.05)
__constant__ float c_alpha[8] = {1.0f, 0.5f, 0.25f, 0.125f, 0.0625f, 0.05f, 0.05f, 0.05f};

// Device globals (allocation-free scratch).
//
// g_sum: 3-buffer rotation; iteration it accumulates into buf it%3 via
// relaxed float red.add. Reads of buf (it%3) happen between barrier it and
// that block's arrival at barrier it+1, so after passing barrier it the bx0
// block may safely zero buf ((it+2)%3) (== buf ((it-1)%3), whose reads all
// completed before barrier it); the zero is release-ordered by bx0's arrival
// at barrier it+1, before any block starts iteration it+2's accumulation.
// Replay safety: it=4 zeroes buf0, it=5 zeroes buf1, next launch's it=0
// zeroes buf2 (before its first use at iteration 2). First launch: static 0.
//
// g_cnt: deferred-reset counters (replay-safe): after passing barrier it,
// bx0 resets counter it-1 (provably no block still polls it); at it=0 it
// resets counter 5 (stale from previous replay; arrivals at counter 5
// require passing barriers 1..4 first, each ordered after the reset).
__device__ float g_sum[3][NMON * BATCH];
__device__ int   g_cnt[NEWTON_ITERS][BATCH];

__device__ __forceinline__ float frcp_approx(float x)
{
    float r;
    asm("rcp.approx.f32 %0, %1;" : "=f"(r) : "f"(x));
    return r;
}
__device__ __forceinline__ void redAddRelaxedF32(float* a, float v)
{
    asm volatile("red.relaxed.gpu.global.add.f32 [%0], %1;" :: "l"(a), "f"(v) : "memory");
}
__device__ __forceinline__ void redAddReleaseS32(int* a, int v)
{
    asm volatile("red.release.gpu.global.add.s32 [%0], %1;" :: "l"(a), "r"(v) : "memory");
}
__device__ __forceinline__ int ldAcquireS32(const int* a)
{
    int v;
    asm volatile("ld.acquire.gpu.global.s32 %0, [%1];" : "=r"(v) : "l"(a) : "memory");
    return v;
}

// ---------------------------------------------------------------------------
// Persistent Newton solver, single launch.
//   g = free*(f - (k*u + 0.4u^3)); h = k + 1.2u^2; du = -g/h
//   monomials G=g, P=u*du^2, Q=du^3 -> 6 sums; trial residual is the exact
//   polynomial r(a) = (1+a)G - 1.2a^2 P - 0.4a^3 Q, so all 8 trial norms^2
//   are quadratic forms in the 6 sums (GG also = init norm^2).
//
//   u, du AND f live in registers for the whole kernel; kd is staged once
//   into shared memory. Iterations 1..5 therefore issue ZERO global loads
//   in the compute phase -> no cross-CTA L1tex-queue contention -> minimal
//   block-to-block spread at each barrier.
//
//   Per-batch barrier: relaxed red.add of the 6 block sums, release-inc of
//   the arrival counter, acquire-poll with nanosleep backoff. No membar.gl
//   anywhere -> no CCTL.IVALL -> caches stay warm across iterations.
__global__ void __launch_bounds__(TPB, 4)
kSolve(const float* __restrict__ f,
       const float* __restrict__ u0,
       const float* __restrict__ kd,
       const int*   __restrict__ fixed_dofs,
       float* __restrict__ out)
{
    const int tid = threadIdx.x;
    const int bx  = blockIdx.x;
    const int b   = blockIdx.y;
    const int i0  = bx * TPB + tid;

    const float4* f4 = reinterpret_cast<const float4*>(f) + (size_t)b * D4;
    const float4* k4 = reinterpret_cast<const float4*>(kd);
    const float4* u4 = reinterpret_cast<const float4*>(u0) + (size_t)b * D4;

    __shared__ float4   sk[CHUNKS * TPB];     // kd slice, 16 KB
    __shared__ uint32_t maskw[CHUNKS * 32];   // 4 ranges x 1024 dofs
    __shared__ float    sred[8][NMON];
    __shared__ float    s_alpha;

    // ---- build this block's fixed-dof bitmap (once) ----
    if (tid < CHUNKS * 32) maskw[tid] = 0u;
    __syncthreads();
    for (int j = tid; j < NFIX; j += TPB) {
        int d = fixed_dofs[j];
#pragma unroll
        for (int c = 0; c < CHUNKS; c++) {
            int lo = (bx * TPB + c * STRIDE) * 4;
            unsigned off = (unsigned)(d - lo);
            if (off < 1024u)
                atomicOr(&maskw[c * 32 + (off >> 5)], 1u << (off & 31));
        }
    }
    __syncthreads();

    // ---- one-time loads: u0 + f -> registers, kd -> shared ----
    uint32_t nibs = 0;   // 4 fixed-bits per chunk
    float u[NV];
    float du[NV];
    float fv[NV];
#pragma unroll
    for (int c = 0; c < CHUNKS; c++) {
        int i  = i0 + c * STRIDE;
        int ic = (i < D4) ? i : (D4 - 1);
        float4 uu = u4[ic];
        float4 ff = f4[ic];
        sk[c * TPB + tid] = k4[ic];
        u[c * 4 + 0]  = uu.x; u[c * 4 + 1]  = uu.y;
        u[c * 4 + 2]  = uu.z; u[c * 4 + 3]  = uu.w;
        fv[c * 4 + 0] = ff.x; fv[c * 4 + 1] = ff.y;
        fv[c * 4 + 2] = ff.z; fv[c * 4 + 3] = ff.w;
        uint32_t w  = maskw[c * 32 + (tid >> 3)];
        uint32_t nb = (w >> ((tid & 7) * 4)) & 0xFu;
        if (i >= D4) nb = 0xFu;            // tail threads contribute nothing
        nibs |= nb << (c * 4);
    }
    __syncthreads();

    for (int it = 0; it < NEWTON_ITERS; it++) {
        float acc[NMON];
#pragma unroll
        for (int m = 0; m < NMON; m++) acc[m] = 0.0f;

        // ---- compute phase: registers + LDS only, no global loads ----
#pragma unroll
        for (int c = 0; c < CHUNKS; c++) {
            float4 kk = sk[c * TPB + tid];
            float ka[4] = {kk.x, kk.y, kk.z, kk.w};
#pragma unroll
            for (int j = 0; j < 4; j++) {
                float fr = ((nibs >> (c * 4 + j)) & 1u) ? 0.0f : 1.0f;
                float uu = u[c * 4 + j];
                float fj = fv[c * 4 + j];
                float u2 = uu * uu;
                float t  = fmaf(0.4f, u2, ka[j]);
                float g  = fr * fmaf(-uu, t, fj);
                float h  = fmaf(1.2f, u2, ka[j]);
                float v  = -g * frcp_approx(h);
                du[c * 4 + j] = v;
                float v2 = v * v;
                float P  = uu * v2;
                float Q  = v * v2;
                acc[0] = fmaf(g, g, acc[0]);
                acc[1] = fmaf(P, P, acc[1]);
                acc[2] = fmaf(Q, Q, acc[2]);
                acc[3] = fmaf(g, P, acc[3]);
                acc[4] = fmaf(g, Q, acc[4]);
                acc[5] = fmaf(P, Q, acc[5]);
            }
        }

        // ---- deterministic block reduction of 6 accumulators ----
#pragma unroll
        for (int m = 0; m < NMON; m++) {
#pragma unroll
            for (int o = 16; o; o >>= 1)
                acc[m] += __shfl_down_sync(0xffffffffu, acc[m], o);
        }
        if ((tid & 31) == 0) {
            int w = tid >> 5;
#pragma unroll
            for (int m = 0; m < NMON; m++) sred[w][m] = acc[m];
        }
        __syncthreads();
        const int buf = it % 3;
        if (tid < NMON) {
            float s = 0.0f;
#pragma unroll
            for (int w = 0; w < 8; w++) s += sred[w][tid];
            redAddRelaxedF32(&g_sum[buf][tid * BATCH + b], s);
        }
        __syncthreads();

        // ---- per-batch barrier: release arrive, acquire poll + backoff ----
        if (tid == 0) {
            redAddReleaseS32(&g_cnt[it][b], 1);
            while (ldAcquireS32(&g_cnt[it][b]) < BX) __nanosleep(64);
        }
        __syncthreads();

        // bx0 housekeeping: reset old counter, zero the it+2 sum buffer.
        // Both are release-ordered by bx0's arrival at barrier it+1.
        if (bx == 0 && tid == 0) {
            int prev = (it == 0) ? (NEWTON_ITERS - 1) : (it - 1);
            __stcg(&g_cnt[prev][b], 0);
            float* z = &g_sum[(it + 2) % 3][0];
#pragma unroll
            for (int m = 0; m < NMON; m++) __stcg(&z[m * BATCH + b], 0.0f);
        }

        // ---- alpha from the 6 global sums (quadratic form per trial) ----
        if (tid == 0) {
            const float* S = &g_sum[buf][0];
            float gg = __ldcg(&S[0 * BATCH + b]);
            float pp = __ldcg(&S[1 * BATCH + b]);
            float qq = __ldcg(&S[2 * BATCH + b]);
            float gp = __ldcg(&S[3 * BATCH + b]);
            float gq = __ldcg(&S[4 * BATCH + b]);
            float pq = __ldcg(&S[5 * BATCH + b]);
            float a = 0.05f;                 // ALPHA_MIN
#pragma unroll
            for (int tr = 7; tr >= 0; tr--) {
                float at = c_alpha[tr];
                float c1 = 1.0f + at;
                float c2 = -1.2f * at * at;
                float c3 = -0.4f * at * at * at;
                float n2 = c1 * c1 * gg + c2 * c2 * pp + c3 * c3 * qq
                         + 2.0f * (c1 * c2 * gp + c1 * c3 * gq + c2 * c3 * pq);
                if (n2 < gg) a = at;         // downward scan -> first improving
            }
            s_alpha = a;
        }
        __syncthreads();

        // ---- update: u += alpha * du ----
        float aB = s_alpha;
#pragma unroll
        for (int x = 0; x < NV; x++)
            u[x] = fmaf(aB, du[x], u[x]);
    }

    // ---- final store ----
    float4* o4 = reinterpret_cast<float4*>(out) + (size_t)b * D4;
#pragma unroll
    for (int c = 0; c < CHUNKS; c++) {
        int i = i0 + c * STRIDE;
        if (i < D4) {
            float4 o = {u[c * 4 + 0], u[c * 4 + 1], u[c * 4 + 2], u[c * 4 + 3]};
            o4[i] = o;
        }
    }
}

// ---------------------------------------------------------------------------
extern "C" void kernel_launch(void* const* d_in, const int* in_sizes, int n_in,
                              void* d_out, int out_size)
{
    const float* f  = (const float*)d_in[0];   // external_forces [B, DOF]
    const float* u0 = (const float*)d_in[1];   // u0              [B, DOF]
    const float* kd = (const float*)d_in[2];   // k_diag          [DOF]
    const int*   fd = (const int*)d_in[3];     // fixed_dofs      [NFIX]

    kSolve<<<dim3(BX, BATCH), TPB>>>(f, u0, kd, fd, (float*)d_out);
}

// round 10
// speedup vs baseline: 1.4673x; 1.3064x over previous
#include <cuda_runtime.h>
#include <stdint.h>

// Problem constants
#define BATCH        8
#define DOF          300000
#define NFIX         3000
#define NEWTON_ITERS 6
#define D4           (DOF / 4)            // 75000 float4 per batch row
#define BX           19                   // blocks per batch row
#define TPB          1024
#define STRIDE       (BX * TPB)           // 19456 float4-threads per batch row
#define CHUNKS       4                    // 4*19456 = 77824 >= 75000
#define NMON         6                    // GG, PP, QQ, GP, GQ, PQ
#define NV           (4 * CHUNKS)         // 16 values per thread
#define NWARP        (TPB / 32)           // 32 warps per block

// Grid = BX*BATCH = 152 blocks = one per GB300 SM, 1024 threads each.
// __launch_bounds__(1024,1): every CTA resident simultaneously (152 SMs,
// >=1 slot each), so the persistent spin-barrier cannot deadlock.

// alphas[t] = max(0.5^t, 0.05)
__constant__ float c_alpha[8] = {1.0f, 0.5f, 0.25f, 0.125f, 0.0625f, 0.05f, 0.05f, 0.05f};

// Device globals (allocation-free scratch).
//
// g_sum: 3-buffer rotation; iteration it accumulates into buf it%3 via
// relaxed float red.add. Reads of buf (it%3) happen between barrier it and
// that block's arrival at barrier it+1, so after passing barrier it the bx0
// block may safely zero buf ((it+2)%3) (== buf ((it-1)%3), whose reads all
// completed before barrier it); the zero is release-ordered by bx0's arrival
// at barrier it+1, before any block starts iteration it+2's accumulation.
// Replay safety: it=4 zeroes buf0, it=5 zeroes buf1, next launch's it=0
// zeroes buf2 (before its first use at iteration 2). First launch: static 0.
//
// g_cnt: deferred-reset counters (replay-safe): after passing barrier it,
// bx0 resets counter it-1 (provably no block still polls it); at it=0 it
// resets counter 5 (stale from previous replay; arrivals at counter 5
// require passing barriers 1..4 first, each ordered after the reset).
__device__ float g_sum[3][NMON * BATCH];
__device__ int   g_cnt[NEWTON_ITERS][BATCH];

__device__ __forceinline__ float frcp_approx(float x)
{
    float r;
    asm("rcp.approx.f32 %0, %1;" : "=f"(r) : "f"(x));
    return r;
}
__device__ __forceinline__ void redAddRelaxedF32(float* a, float v)
{
    asm volatile("red.relaxed.gpu.global.add.f32 [%0], %1;" :: "l"(a), "f"(v) : "memory");
}
__device__ __forceinline__ void redAddReleaseS32(int* a, int v)
{
    asm volatile("red.release.gpu.global.add.s32 [%0], %1;" :: "l"(a), "r"(v) : "memory");
}
__device__ __forceinline__ int ldAcquireS32(const int* a)
{
    int v;
    asm volatile("ld.acquire.gpu.global.s32 %0, [%1];" : "=r"(v) : "l"(a) : "memory");
    return v;
}

// ---------------------------------------------------------------------------
// Persistent Newton solver, single launch, ONE CTA PER SM.
//   g = free*(f - (k*u + 0.4u^3)); h = k + 1.2u^2; du = -g/h
//   monomials G=g, P=u*du^2, Q=du^3 -> 6 sums; trial residual is the exact
//   polynomial r(a) = (1+a)G - 1.2a^2 P - 0.4a^3 Q, so all 8 trial norms^2
//   are quadratic forms in the 6 sums (GG also = init norm^2).
//   u and du live in registers; f/kd reload from an L1-resident working set
//   (no membar.gl anywhere -> no CCTL.IVALL -> L1 never flushed).
//   Per-batch barrier: relaxed red.add of the 6 block sums, release-inc of
//   the arrival counter (fan-in only 19), acquire-poll with nanosleep.
__global__ void __launch_bounds__(TPB, 1)
kSolve(const float* __restrict__ f,
       const float* __restrict__ u0,
       const float* __restrict__ kd,
       const int*   __restrict__ fixed_dofs,
       float* __restrict__ out)
{
    const int tid = threadIdx.x;
    const int bx  = blockIdx.x;
    const int b   = blockIdx.y;
    const int i0  = bx * TPB + tid;

    const float4* f4 = reinterpret_cast<const float4*>(f) + (size_t)b * D4;
    const float4* k4 = reinterpret_cast<const float4*>(kd);
    const float4* u4 = reinterpret_cast<const float4*>(u0) + (size_t)b * D4;

    __shared__ uint32_t maskw[CHUNKS * (TPB / 8)];  // 4 ranges x 4096 dofs -> 512 words
    __shared__ float    sred[NWARP][NMON];
    __shared__ float    s_alpha;

    // ---- build this block's fixed-dof bitmap (once) ----
    for (int j = tid; j < CHUNKS * (TPB / 8); j += TPB) maskw[j] = 0u;
    __syncthreads();
    for (int j = tid; j < NFIX; j += TPB) {
        int d = fixed_dofs[j];
#pragma unroll
        for (int c = 0; c < CHUNKS; c++) {
            int lo = (bx * TPB + c * STRIDE) * 4;
            unsigned off = (unsigned)(d - lo);
            if (off < (unsigned)(TPB * 4))
                atomicOr(&maskw[c * (TPB / 8) + (off >> 5)], 1u << (off & 31));
        }
    }
    __syncthreads();

    uint32_t nibs = 0;   // 4 fixed-bits per chunk
    float u[NV];
    float du[NV];
#pragma unroll
    for (int c = 0; c < CHUNKS; c++) {
        int i  = i0 + c * STRIDE;
        int ic = (i < D4) ? i : (D4 - 1);
        float4 uu = u4[ic];
        u[c * 4 + 0] = uu.x; u[c * 4 + 1] = uu.y;
        u[c * 4 + 2] = uu.z; u[c * 4 + 3] = uu.w;
        uint32_t w  = maskw[c * (TPB / 8) + (tid >> 3)];
        uint32_t nb = (w >> ((tid & 7) * 4)) & 0xFu;
        if (i >= D4) nb = 0xFu;            // tail threads contribute nothing
        nibs |= nb << (c * 4);
    }

    for (int it = 0; it < NEWTON_ITERS; it++) {
        float acc[NMON];
#pragma unroll
        for (int m = 0; m < NMON; m++) acc[m] = 0.0f;

        // ---- compute monomial partial sums; du stays in registers ----
#pragma unroll
        for (int c = 0; c < CHUNKS; c++) {
            int i  = i0 + c * STRIDE;
            int ic = (i < D4) ? i : (D4 - 1);
            float4 ff = f4[ic];
            float4 kk = k4[ic];
            float fa[4] = {ff.x, ff.y, ff.z, ff.w};
            float ka[4] = {kk.x, kk.y, kk.z, kk.w};
#pragma unroll
            for (int j = 0; j < 4; j++) {
                float fr = ((nibs >> (c * 4 + j)) & 1u) ? 0.0f : 1.0f;
                float uu = u[c * 4 + j];
                float u2 = uu * uu;
                float t  = fmaf(0.4f, u2, ka[j]);
                float g  = fr * fmaf(-uu, t, fa[j]);
                float h  = fmaf(1.2f, u2, ka[j]);
                float v  = -g * frcp_approx(h);
                du[c * 4 + j] = v;
                float v2 = v * v;
                float P  = uu * v2;
                float Q  = v * v2;
                acc[0] = fmaf(g, g, acc[0]);
                acc[1] = fmaf(P, P, acc[1]);
                acc[2] = fmaf(Q, Q, acc[2]);
                acc[3] = fmaf(g, P, acc[3]);
                acc[4] = fmaf(g, Q, acc[4]);
                acc[5] = fmaf(P, Q, acc[5]);
            }
        }

        // ---- deterministic block reduction of 6 accumulators ----
#pragma unroll
        for (int m = 0; m < NMON; m++) {
#pragma unroll
            for (int o = 16; o; o >>= 1)
                acc[m] += __shfl_down_sync(0xffffffffu, acc[m], o);
        }
        if ((tid & 31) == 0) {
            int w = tid >> 5;
#pragma unroll
            for (int m = 0; m < NMON; m++) sred[w][m] = acc[m];
        }
        __syncthreads();
        const int buf = it % 3;
        if (tid < NMON) {
            float s = 0.0f;
#pragma unroll
            for (int w = 0; w < NWARP; w++) s += sred[w][tid];
            redAddRelaxedF32(&g_sum[buf][tid * BATCH + b], s);
        }
        __syncthreads();

        // ---- per-batch barrier: release arrive, acquire poll + backoff ----
        if (tid == 0) {
            redAddReleaseS32(&g_cnt[it][b], 1);
            while (ldAcquireS32(&g_cnt[it][b]) < BX) __nanosleep(64);
        }
        __syncthreads();

        // ---- alpha from the 6 global sums (quadratic form per trial) ----
        if (tid == 0) {
            const float* S = &g_sum[buf][0];
            float gg = __ldcg(&S[0 * BATCH + b]);
            float pp = __ldcg(&S[1 * BATCH + b]);
            float qq = __ldcg(&S[2 * BATCH + b]);
            float gp = __ldcg(&S[3 * BATCH + b]);
            float gq = __ldcg(&S[4 * BATCH + b]);
            float pq = __ldcg(&S[5 * BATCH + b]);
            float a = 0.05f;                 // ALPHA_MIN
#pragma unroll
            for (int tr = 7; tr >= 0; tr--) {
                float at = c_alpha[tr];
                float c1 = 1.0f + at;
                float c2 = -1.2f * at * at;
                float c3 = -0.4f * at * at * at;
                float n2 = c1 * c1 * gg + c2 * c2 * pp + c3 * c3 * qq
                         + 2.0f * (c1 * c2 * gp + c1 * c3 * gq + c2 * c3 * pq);
                if (n2 < gg) a = at;         // downward scan -> first improving
            }
            s_alpha = a;
        }

        // bx0 housekeeping off the critical path: reset old counter, zero
        // the it+2 sum buffer. Release-ordered by bx0's arrival at it+1.
        if (bx == 0 && tid == 32) {
            int prev = (it == 0) ? (NEWTON_ITERS - 1) : (it - 1);
            __stcg(&g_cnt[prev][b], 0);
            float* z = &g_sum[(it + 2) % 3][0];
#pragma unroll
            for (int m = 0; m < NMON; m++) __stcg(&z[m * BATCH + b], 0.0f);
        }
        __syncthreads();

        // ---- update: u += alpha * du ----
        float aB = s_alpha;
#pragma unroll
        for (int x = 0; x < NV; x++)
            u[x] = fmaf(aB, du[x], u[x]);
    }

    // ---- final store ----
    float4* o4 = reinterpret_cast<float4*>(out) + (size_t)b * D4;
#pragma unroll
    for (int c = 0; c < CHUNKS; c++) {
        int i = i0 + c * STRIDE;
        if (i < D4) {
            float4 o = {u[c * 4 + 0], u[c * 4 + 1], u[c * 4 + 2], u[c * 4 + 3]};
            o4[i] = o;
        }
    }
}

// ---------------------------------------------------------------------------
extern "C" void kernel_launch(void* const* d_in, const int* in_sizes, int n_in,
                              void* d_out, int out_size)
{
    const float* f  = (const float*)d_in[0];   // external_forces [B, DOF]
    const float* u0 = (const float*)d_in[1];   // u0              [B, DOF]
    const float* kd = (const float*)d_in[2];   // k_diag          [DOF]
    const int*   fd = (const int*)d_in[3];     // fixed_dofs      [NFIX]

    kSolve<<<dim3(BX, BATCH), TPB>>>(f, u0, kd, fd, (float*)d_out);
}